// round 3
// baseline (speedup 1.0000x reference)
#include <cuda_runtime.h>
#include <cstdint>

// Problem constants
#define NB    1024
#define NTCR  100
#define NFEAT 15
#define NAA   24
#define NCH   14          // total conv output channels
#define NINST (NB*NTCR)   // 102400
#define NPAIR (NINST/2)   // 51200  (two instances packed per f32x2 lane)
#define PAIRS_PER_BLOCK 8 // 4 warps * 2 pairs
#define NBLK_CONV (NPAIR/PAIRS_PER_BLOCK) // 6400

// ---------------- scratch (static device memory; no allocation) ----------------
__device__ float2 g_hbuf[NPAIR * NCH];          // h vectors, packed (instA, instB)
__device__ float2 g_sbuf[NPAIR];                // attention scores, packed
__device__ float  g_zbuf[NB * NCH];             // decoder_f output (pre-BN)
__device__ unsigned long long g_wpack[1470 + 14]; // staged packed conv weights+bias

// Conv weights (duplicated into both f32x2 halves) in constant memory:
// layout [(c*7 + t)*14 + ch], then 14 biases at offset 1470.
__constant__ unsigned long long cW[1484];

// ---------------- helpers ----------------
__device__ __forceinline__ unsigned long long ffma2(unsigned long long a,
                                                    unsigned long long b,
                                                    unsigned long long c) {
    unsigned long long d;
    asm("fma.rn.f32x2 %0, %1, %2, %3;" : "=l"(d) : "l"(a), "l"(b), "l"(c));
    return d;
}
__device__ __forceinline__ float lo2(unsigned long long v) {
    return __uint_as_float((unsigned)(v & 0xffffffffull));
}
__device__ __forceinline__ float hi2(unsigned long long v) {
    return __uint_as_float((unsigned)(v >> 32));
}
__device__ __forceinline__ unsigned long long pack2(float a, float b) {
    return ((unsigned long long)__float_as_uint(b) << 32) | __float_as_uint(a);
}

// ---------------- prep: pack conv weights into staging buffer ----------------
__global__ void prepKernel(const float* __restrict__ w0, const float* __restrict__ b0,
                           const float* __restrict__ w1, const float* __restrict__ b1,
                           const float* __restrict__ w2, const float* __restrict__ b2,
                           const float* __restrict__ w3, const float* __restrict__ b3,
                           const float* __restrict__ w4, const float* __restrict__ b4,
                           const float* __restrict__ w5, const float* __restrict__ b5) {
    const int chH[14]    = {2,2,2,3,3,3,4,4,4,5,5,6,6,7};
    const int chF[14]    = {0,1,2,0,1,2,0,1,2,0,1,0,1,0};
    const int chConv[14] = {0,0,0,1,1,1,2,2,2,3,3,4,4,5};
    const float* cws[6] = {w0,w1,w2,w3,w4,w5};
    const float* cbs[6] = {b0,b1,b2,b3,b4,b5};
    int idx = blockIdx.x * blockDim.x + threadIdx.x;
    if (idx < 1470) {
        int ch = idx % 14;
        int r  = idx / 14;
        int t  = r % 7;
        int c  = r / 7;
        int h  = chH[ch];
        float w = 0.0f;
        if (t < h) {
            const float* W = cws[chConv[ch]];
            w = W[(chF[ch] * NFEAT + c) * h + t];
        }
        g_wpack[idx] = pack2(w, w);
    } else if (idx < 1484) {
        int ch = idx - 1470;
        float b = cbs[chConv[ch]][chF[ch]];
        g_wpack[idx] = pack2(b, b);
    }
}

// ---------------- stage 1: conv + relu + maxpool + fc1 + relu + score ----------------
__global__ void __launch_bounds__(128) convKernel(const float* __restrict__ x,
                                                  const float* __restrict__ fc1w,
                                                  const float* __restrict__ fc1b,
                                                  const float* __restrict__ waw) {
    __shared__ unsigned long long xs[4][2][452]; // [warp][pp][15 rows * stride30 + pad]
    __shared__ float fcw[196];
    __shared__ float fcb[14];
    __shared__ float wav[14];

    int tid  = threadIdx.x;
    int w    = tid >> 5;
    int lane = tid & 31;
    // BUGFIX (R1/R2 root cause): block has 128 threads, fcw has 196 entries —
    // the old `if (tid < 196)` left fcw[128..195] uninitialized garbage.
    for (int i = tid; i < 196; i += 128) fcw[i] = fc1w[i];
    if (tid < 14)  { fcb[tid] = fc1b[tid]; wav[tid] = waw[tid]; }

    int pairBase = blockIdx.x * PAIRS_PER_BLOCK + w * 2;

    // zero-pad then fill x tiles (2 pairs = 4 instances, packed 2-wide)
    #pragma unroll
    for (int pp = 0; pp < 2; ++pp) {
        unsigned long long* xw = xs[w][pp];
        for (int i = lane; i < 452; i += 32) xw[i] = 0ull;
    }
    __syncwarp();
    #pragma unroll
    for (int pp = 0; pp < 2; ++pp) {
        const float* xg = x + (size_t)(pairBase + pp) * 720;
        unsigned long long* xw = xs[w][pp];
        for (int i = lane; i < 360; i += 32) {
            int c = i / 24;
            int a = i - c * 24;
            xw[c * 30 + a] = pack2(xg[i], xg[360 + i]);
        }
    }
    __syncthreads();

    int lp = (lane < 24) ? lane : 0;
    unsigned long long a0[14], a1[14];
    #pragma unroll
    for (int ch = 0; ch < 14; ++ch) { a0[ch] = 0ull; a1[ch] = 0ull; }

    const unsigned long long* x0 = xs[w][0] + lp;
    const unsigned long long* x1 = xs[w][1] + lp;
    constexpr int CS[7] = {0, 0, 3, 6, 9, 11, 13}; // first active channel per tap

    #pragma unroll 1
    for (int c = 0; c < 15; ++c) {
        #pragma unroll
        for (int t = 0; t < 7; ++t) {
            unsigned long long xv0 = x0[c * 30 + t];
            unsigned long long xv1 = x1[c * 30 + t];
            #pragma unroll
            for (int ch = CS[t]; ch < 14; ++ch) {
                unsigned long long wv = cW[(c * 7 + t) * 14 + ch];
                a0[ch] = ffma2(wv, xv0, a0[ch]);
                a1[ch] = ffma2(wv, xv1, a1[ch]);
            }
        }
    }

    // bias + relu + masked global max over positions
    constexpr int chHt[14] = {2,2,2,3,3,3,4,4,4,5,5,6,6,7};
    float f0x[14], f0y[14], f1x[14], f1y[14];
    #pragma unroll
    for (int ch = 0; ch < 14; ++ch) {
        float bb  = lo2(cW[1470 + ch]);
        float vx0 = fmaxf(lo2(a0[ch]) + bb, 0.0f);
        float vy0 = fmaxf(hi2(a0[ch]) + bb, 0.0f);
        float vx1 = fmaxf(lo2(a1[ch]) + bb, 0.0f);
        float vy1 = fmaxf(hi2(a1[ch]) + bb, 0.0f);
        if (lane > 24 - chHt[ch]) { vx0 = 0.0f; vy0 = 0.0f; vx1 = 0.0f; vy1 = 0.0f; }
        #pragma unroll
        for (int off = 16; off; off >>= 1) {
            vx0 = fmaxf(vx0, __shfl_xor_sync(0xffffffffu, vx0, off));
            vy0 = fmaxf(vy0, __shfl_xor_sync(0xffffffffu, vy0, off));
            vx1 = fmaxf(vx1, __shfl_xor_sync(0xffffffffu, vx1, off));
            vy1 = fmaxf(vy1, __shfl_xor_sync(0xffffffffu, vy1, off));
        }
        f0x[ch] = vx0; f0y[ch] = vy0; f1x[ch] = vx1; f1y[ch] = vy1;
    }

    // fc1 + relu + attention score: lanes 0..13 -> pair pp0, lanes 16..29 -> pair pp1
    int g = lane >> 4;   // which pair
    int j = lane & 15;   // output dim
    float hx = 0.0f, hy = 0.0f;
    if (j < 14) { hx = fcb[j]; hy = fcb[j]; }
    #pragma unroll
    for (int k = 0; k < 14; ++k) {
        float fx = g ? f1x[k] : f0x[k];
        float fy = g ? f1y[k] : f0y[k];
        float ww = 0.0f;
        if (j < 14) ww = fcw[j * 14 + k];
        hx = fmaf(ww, fx, hx);
        hy = fmaf(ww, fy, hy);
    }
    hx = fmaxf(hx, 0.0f);
    hy = fmaxf(hy, 0.0f);
    float px = 0.0f, py = 0.0f;
    if (j < 14) { float wa = wav[j]; px = hx * wa; py = hy * wa; }
    #pragma unroll
    for (int off = 1; off < 16; off <<= 1) {
        px += __shfl_xor_sync(0xffffffffu, px, off);
        py += __shfl_xor_sync(0xffffffffu, py, off);
    }
    int pair = pairBase + g;
    if (j < 14) g_hbuf[pair * 14 + j] = make_float2(hx, hy);
    if (j == 0) g_sbuf[pair] = make_float2(px, py);
}

// ---------------- stage 2: sparsemax + pooled + decoder_f (one block per repertoire) ----------------
__global__ void __launch_bounds__(128) attnKernel(const float* __restrict__ decfw,
                                                  const float* __restrict__ decfb,
                                                  float* __restrict__ out,
                                                  int write_attw) {
    __shared__ float z[100];
    __shared__ float zsrt[100];
    __shared__ float aw[100];
    __shared__ float2 hsh[700];
    __shared__ float pooled[14];
    __shared__ float tau_s;

    int b = blockIdx.x;
    int t = threadIdx.x;

    if (t < 50) {
        float2 s2 = g_sbuf[b * 50 + t];
        z[2 * t]     = s2.x;
        z[2 * t + 1] = s2.y;
    }
    for (int i = t; i < 700; i += 128) hsh[i] = g_hbuf[b * 700 + i];
    __syncthreads();

    // exact O(n^2) rank sort (descending, stable)
    if (t < 100) {
        float zi = z[t];
        int r = 0;
        for (int j2 = 0; j2 < 100; ++j2) {
            float zj = z[j2];
            r += (int)(zj > zi) | ((int)(zj == zi) & (int)(j2 < t));
        }
        zsrt[r] = zi;
    }
    __syncthreads();

    if (t == 0) {
        float cs = 0.0f, cssel = 0.0f;
        int ks = 1;
        for (int i = 0; i < 100; ++i) {
            cs += zsrt[i];
            if (1.0f + (float)(i + 1) * zsrt[i] > cs) { ks = i + 1; cssel = cs; }
        }
        tau_s = (cssel - 1.0f) / (float)ks;
    }
    __syncthreads();

    float tau = tau_s;
    if (t < 100) {
        float a = fmaxf(z[t] - tau, 0.0f);
        aw[t] = a;
        // attw is only part of the harness output when out_size covers it;
        // writing it unconditionally would be OOB if output is logits-only.
        if (write_attw) out[2048 + b * 100 + t] = a;
    }
    __syncthreads();

    if (t < 14) {
        float acc = 0.0f;
        #pragma unroll 5
        for (int p = 0; p < 50; ++p) {
            float2 h2 = hsh[p * 14 + t];
            acc = fmaf(aw[2 * p],     h2.x, acc);
            acc = fmaf(aw[2 * p + 1], h2.y, acc);
        }
        pooled[t] = acc;
    }
    __syncthreads();

    if (t < 14) {
        float zz = decfb[t];
        #pragma unroll
        for (int k = 0; k < 14; ++k) zz = fmaf(decfw[t * 14 + k], pooled[k], zz);
        g_zbuf[b * 14 + t] = zz;
    }
}

// ---------------- stage 3: batchnorm (batch stats) + relu + decoder_s ----------------
__global__ void __launch_bounds__(1024) bnKernel(const float* __restrict__ bng,
                                                 const float* __restrict__ bnb,
                                                 const float* __restrict__ dsw,
                                                 const float* __restrict__ dsb,
                                                 float* __restrict__ out) {
    __shared__ float ssum[32][14];
    __shared__ float ssq[32][14];
    __shared__ float mu[14];
    __shared__ float sc[14];

    int b    = threadIdx.x;
    int w    = b >> 5;
    int lane = b & 31;

    float zr[14];
    #pragma unroll
    for (int j = 0; j < 14; ++j) zr[j] = g_zbuf[b * 14 + j];

    #pragma unroll
    for (int j = 0; j < 14; ++j) {
        float s = zr[j];
        float q = zr[j] * zr[j];
        #pragma unroll
        for (int off = 16; off; off >>= 1) {
            s += __shfl_xor_sync(0xffffffffu, s, off);
            q += __shfl_xor_sync(0xffffffffu, q, off);
        }
        if (lane == 0) { ssum[w][j] = s; ssq[w][j] = q; }
    }
    __syncthreads();

    if (b < 14) {
        float s = 0.0f, q = 0.0f;
        #pragma unroll
        for (int i = 0; i < 32; ++i) { s += ssum[i][b]; q += ssq[i][b]; }
        float m = s * (1.0f / 1024.0f);
        float v = q * (1.0f / 1024.0f) - m * m;
        mu[b] = m;
        sc[b] = bng[b] * rsqrtf(v + 1e-5f);
    }
    __syncthreads();

    float l0 = dsb[0], l1 = dsb[1];
    #pragma unroll
    for (int j = 0; j < 14; ++j) {
        float zn = fmaxf((zr[j] - mu[j]) * sc[j] + bnb[j], 0.0f);
        l0 = fmaf(dsw[j],      zn, l0);
        l1 = fmaf(dsw[14 + j], zn, l1);
    }
    out[b * 2]     = l0;
    out[b * 2 + 1] = l1;
}

// ---------------- launch ----------------
extern "C" void kernel_launch(void* const* d_in, const int* in_sizes, int n_in,
                              void* d_out, int out_size) {
    // Input index maps: insertion order (setup_inputs dict order) vs
    // alphabetized metadata. Detect via the unmistakable x element count.
    // insertion: x,cw0,cb0,...,cw5,cb5,fc1_w,fc1_b,waout_w,decf_w,decf_b,bn_g,bn_b,decs_w,decs_b
    static const int MAP_INS[22] = {0,1,2,3,4,5,6,7,8,9,10,11,12,13,14,15,16,17,18,19,20,21};
    // alphabetical: bn_b,bn_g,cb0..cb5,cw0..cw5,decf_b,decf_w,decs_b,decs_w,fc1_b,fc1_w,waout_w,x
    // (index of each logical slot in the alphabetical list)
    //                       x  cw0 cb0 cw1 cb1 cw2 cb2 cw3 cb3 cw4 cb4 cw5 cb5 f1w f1b waw dfw dfb bng bnb dsw dsb
    static const int MAP_AL[22] = {21, 8,  2,  9,  3, 10,  4, 11,  5, 12,  6, 13,  7, 19, 18, 20, 15, 14,  1,  0, 17, 16};

    const int* M = MAP_INS;
    if (n_in >= 22 && in_sizes[0] != NINST * NFEAT * NAA && in_sizes[21] == NINST * NFEAT * NAA) {
        M = MAP_AL;
    }

    const float* x    = (const float*)d_in[M[0]];
    const float* cw0  = (const float*)d_in[M[1]];
    const float* cb0  = (const float*)d_in[M[2]];
    const float* cw1  = (const float*)d_in[M[3]];
    const float* cb1  = (const float*)d_in[M[4]];
    const float* cw2  = (const float*)d_in[M[5]];
    const float* cb2  = (const float*)d_in[M[6]];
    const float* cw3  = (const float*)d_in[M[7]];
    const float* cb3  = (const float*)d_in[M[8]];
    const float* cw4  = (const float*)d_in[M[9]];
    const float* cb4  = (const float*)d_in[M[10]];
    const float* cw5  = (const float*)d_in[M[11]];
    const float* cb5  = (const float*)d_in[M[12]];
    const float* fc1w = (const float*)d_in[M[13]];
    const float* fc1b = (const float*)d_in[M[14]];
    const float* waw  = (const float*)d_in[M[15]];
    const float* dfw  = (const float*)d_in[M[16]];
    const float* dfb  = (const float*)d_in[M[17]];
    const float* bng  = (const float*)d_in[M[18]];
    const float* bnb  = (const float*)d_in[M[19]];
    const float* dsw  = (const float*)d_in[M[20]];
    const float* dsb  = (const float*)d_in[M[21]];
    float* out = (float*)d_out;

    // Only emit attw if the output buffer actually has room for it
    // (logits = 2048 floats, attw = 102400 floats).
    int write_attw = (out_size >= 2048 + NB * NTCR) ? 1 : 0;

    prepKernel<<<6, 256>>>(cw0, cb0, cw1, cb1, cw2, cb2, cw3, cb3, cw4, cb4, cw5, cb5);

    void* src = nullptr;
    cudaGetSymbolAddress(&src, g_wpack);
    cudaMemcpyToSymbolAsync(cW, src, sizeof(g_wpack), 0, cudaMemcpyDeviceToDevice, 0);

    convKernel<<<NBLK_CONV, 128>>>(x, fc1w, fc1b, waw);
    attnKernel<<<NB, 128>>>(dfw, dfb, out, write_attw);
    bnKernel<<<1, 1024>>>(bng, bnb, dsw, dsb, out);
}